// round 7
// baseline (speedup 1.0000x reference)
#include <cuda_runtime.h>
#include <cuda_fp16.h>
#include <stdint.h>

// CosRec fused kernel — fp16 mma.sync (HMMA), round 7.
// vs round 5: conflict-free transposed half2 tables (stride 60).
// vs round 6: reverted to single-accumulator 8-m-tile mainloop (regs ~127),
// smem cut to 50.4 KB (no W1 staging; bfrag overlays dead sAf/sBf) so
// 2 CTAs/SM fit -> 16 warps/SM for latency hiding.

#define THREADS 256
#define TSTR 60            // table row stride in words (conflict-free)

// ---- shared memory byte offsets ----
#define OFF_SI    0        // 36 ints
#define OFF_SX    160      // 164 floats (ends 816)
#define OFF_A2    1024     // uint32 A-table [32 c][60] = 7680 B
#define OFF_B2    8704     // uint32 B-table [32 a][60] = 7680 B
#define OFF_Y     16384    // sAf[12800]+sBf[12800]; later bfragW (23296 B)
#define OFF_ET    41984    // fp32 E^T [64][33] = 8448 B ; later sRedW[8][104]
#define SMEM_TOTAL 50432

__device__ __forceinline__ void mma16816(float* d, uint32_t a0, uint32_t a1,
                                         uint32_t a2, uint32_t a3,
                                         uint32_t b0, uint32_t b1) {
    asm volatile(
        "mma.sync.aligned.m16n8k16.row.col.f32.f16.f16.f32 "
        "{%0,%1,%2,%3}, {%4,%5,%6,%7}, {%8,%9}, {%0,%1,%2,%3};"
        : "+f"(d[0]), "+f"(d[1]), "+f"(d[2]), "+f"(d[3])
        : "r"(a0), "r"(a1), "r"(a2), "r"(a3), "r"(b0), "r"(b1));
}

__device__ __forceinline__ uint32_t hbuild(uint32_t a, uint32_t b) {
    __half2 av = *reinterpret_cast<__half2*>(&a);
    __half2 bv = *reinterpret_cast<__half2*>(&b);
    __half2 r  = __hmax2(__hadd2(av, bv), __float2half2_rn(0.0f));
    return *reinterpret_cast<uint32_t*>(&r);
}

__global__ __launch_bounds__(THREADS, 2)
void cosrec_kernel(
    const int*   __restrict__ seq_var,   // [512*32]
    const int*   __restrict__ user_var,  // [512]
    const int*   __restrict__ item_var,  // [512*3]
    const float* __restrict__ item_emb,  // [100000*64]
    const float* __restrict__ user_emb,  // [100000*64]
    const float* __restrict__ W2,        // [100000*164]
    const float* __restrict__ b2,        // [100000]
    const float* __restrict__ W1,        // [100*128]
    const float* __restrict__ b1,        // [100]
    const float* __restrict__ Wf2,       // [100*100]
    const float* __restrict__ bf2,       // [100]
    float*       __restrict__ out)       // [512*3]
{
    extern __shared__ char smem[];
    int*      sI  = (int*)(smem + OFF_SI);
    float*    sX  = (float*)(smem + OFF_SX);
    uint32_t* uA2 = (uint32_t*)(smem + OFF_A2);
    uint32_t* uB2 = (uint32_t*)(smem + OFF_B2);
    float*    sAf = (float*)(smem + OFF_Y);            // [100][32]
    float*    sBf = (float*)(smem + OFF_Y + 12800);    // [100][32]
    float*    sEt = (float*)(smem + OFF_ET);

    const int b    = blockIdx.x;
    const int tid  = threadIdx.x;
    const int wid  = tid >> 5;
    const int lane = tid & 31;

    // ---- phase 0: indices ----
    if (tid < 32)       sI[tid] = seq_var[b * 32 + tid];
    else if (tid < 35)  sI[tid] = item_var[b * 3 + (tid - 32)];
    else if (tid == 35) sI[35]  = user_var[b];
    __syncthreads();

    // ---- phase 1: gather E^T ----
    for (int idx = tid; idx < 2048; idx += THREADS) {
        int l = idx >> 6, d = idx & 63;
        sEt[d * 33 + l] = item_emb[(size_t)sI[l] * 64 + d];
    }
    __syncthreads();

    // ---- phase 2: A = E@Wa^T + b1, B = E@Wb^T ----
    // f = idx>>5 is warp-uniform -> W1/b1 reads are warp-broadcast LDG (L2-hot).
    for (int idx = tid; idx < 3200; idx += THREADS) {
        int f = idx >> 5, l = idx & 31;
        const float* w1r = W1 + f * 128;
        float accA = 0.0f, accB = 0.0f;
        #pragma unroll 8
        for (int j = 0; j < 64; ++j) {
            float e = sEt[j * 33 + l];
            accA = fmaf(e, __ldg(w1r + j),      accA);
            accB = fmaf(e, __ldg(w1r + 64 + j), accB);
        }
        sAf[idx] = accA + __ldg(b1 + f);
        sBf[idx] = accB;
    }
    __syncthreads();

    // ---- phase 3a: pack half2 tables, transposed [c][k2], stride 60 ----
    // k2 < 50: real (k=2*k2, 2*k2+1). k2 == 50: bias col (A=(1,0), B=(0,0)).
    // k2 in (50,56): zero padding.
    for (int idx = tid; idx < 32 * 56; idx += THREADS) {
        int c = idx / 56, kk = idx - c * 56;
        __half2 va, vb;
        if (kk < 50) {
            va = __floats2half2_rn(sAf[(2 * kk) * 32 + c], sAf[(2 * kk + 1) * 32 + c]);
            vb = __floats2half2_rn(sBf[(2 * kk) * 32 + c], sBf[(2 * kk + 1) * 32 + c]);
        } else if (kk == 50) {
            va = __floats2half2_rn(1.0f, 0.0f);
            vb = __float2half2_rn(0.0f);
        } else {
            va = __float2half2_rn(0.0f);
            vb = __float2half2_rn(0.0f);
        }
        uA2[c * TSTR + kk] = *reinterpret_cast<uint32_t*>(&va);
        uB2[c * TSTR + kk] = *reinterpret_cast<uint32_t*>(&vb);
    }
    __syncthreads();   // sAf/sBf dead; bfragW overlays them

    // ---- phase 3b: pack Wf2 B-fragments (mma fragment order, col-major B) ----
    // W(n,k): n<100 & k<100 -> Wf2[n][k]; n<100 & k==100 -> bf2[n]; else 0.
    uint2* bfragW = (uint2*)(smem + OFF_Y);
    for (int idx = tid; idx < 13 * 7 * 32; idx += THREADS) {
        int nt  = idx / 224;
        int rem = idx - nt * 224;
        int ks  = rem >> 5, ln = rem & 31;
        int n   = nt * 8 + (ln >> 2);
        int k0  = ks * 16 + (ln & 3) * 2;
        float w0, w1, w2v, w3v;
        if (n < 100) {
            const float* wr = Wf2 + n * 100;
            w0  = (k0     < 100) ? wr[k0]     : ((k0     == 100) ? bf2[n] : 0.0f);
            w1  = (k0 + 1 < 100) ? wr[k0 + 1] : ((k0 + 1 == 100) ? bf2[n] : 0.0f);
            w2v = (k0 + 8 < 100) ? wr[k0 + 8] : ((k0 + 8 == 100) ? bf2[n] : 0.0f);
            w3v = (k0 + 9 < 100) ? wr[k0 + 9] : ((k0 + 9 == 100) ? bf2[n] : 0.0f);
        } else {
            w0 = w1 = w2v = w3v = 0.0f;
        }
        __half2 lo = __floats2half2_rn(w0, w1);
        __half2 hi = __floats2half2_rn(w2v, w3v);
        uint2 val;
        val.x = *reinterpret_cast<uint32_t*>(&lo);
        val.y = *reinterpret_cast<uint32_t*>(&hi);
        bfragW[idx] = val;
    }
    __syncthreads();

    // ---- mainloop: 8 m-tiles of 16 pairs per warp; no CTA syncs ----
    const int gid = lane >> 2;   // row group 0..7
    const int tig = lane & 3;    // k group 0..3

    float xacc[26];
    #pragma unroll
    for (int j = 0; j < 26; ++j) xacc[j] = 0.0f;

    for (int mt = 0; mt < 8; ++mt) {
        // pair p0 = wid*128 + mt*16 + gid, p1 = p0 + 8; same a-block, c split.
        const int p0 = wid * 128 + mt * 16 + gid;
        const int aI = p0 >> 5;
        const int cA = p0 & 31;
        const int cB = cA + 8;

        float acc[13][4];
        #pragma unroll
        for (int nt = 0; nt < 13; ++nt)
            #pragma unroll
            for (int e = 0; e < 4; ++e) acc[nt][e] = 0.0f;

        #pragma unroll
        for (int ks = 0; ks < 7; ++ks) {
            const int k2a = ks * 8 + tig;
            const int k2b = k2a + 4;
            uint32_t Ba = uB2[aI * TSTR + k2a];
            uint32_t Bb = uB2[aI * TSTR + k2b];
            uint32_t a0 = hbuild(uA2[cA * TSTR + k2a], Ba);
            uint32_t a1 = hbuild(uA2[cB * TSTR + k2a], Ba);
            uint32_t a2 = hbuild(uA2[cA * TSTR + k2b], Bb);
            uint32_t a3 = hbuild(uA2[cB * TSTR + k2b], Bb);
            #pragma unroll
            for (int nt = 0; nt < 13; ++nt) {
                uint2 bb = bfragW[(nt * 7 + ks) * 32 + lane];
                mma16816(acc[nt], a0, a1, a2, a3, bb.x, bb.y);
            }
        }
        // relu + colsum into registers (rows p0 and p1)
        #pragma unroll
        for (int nt = 0; nt < 13; ++nt) {
            xacc[nt * 2]     += fmaxf(acc[nt][0], 0.0f) + fmaxf(acc[nt][2], 0.0f);
            xacc[nt * 2 + 1] += fmaxf(acc[nt][1], 0.0f) + fmaxf(acc[nt][3], 0.0f);
        }
    }

    // ---- reduction: shfl over row/k groups, then fixed-order over warps ----
    #pragma unroll
    for (int j = 0; j < 26; ++j) {
        float s = xacc[j];
        s += __shfl_down_sync(0xffffffffu, s, 16);
        s += __shfl_down_sync(0xffffffffu, s, 8);
        s += __shfl_down_sync(0xffffffffu, s, 4);
        xacc[j] = s;
    }
    float* sRedW = (float*)(smem + OFF_ET);  // [8][104], overlays dead E^T
    if (lane < 4) {
        #pragma unroll
        for (int nt = 0; nt < 13; ++nt) {
            int n0 = nt * 8 + lane * 2;      // lane == tig here
            sRedW[wid * 104 + n0]     = xacc[nt * 2];
            sRedW[wid * 104 + n0 + 1] = xacc[nt * 2 + 1];
        }
    }
    __syncthreads();
    if (tid < 100) {
        float s = 0.0f;
        #pragma unroll
        for (int w = 0; w < 8; ++w) s += sRedW[w * 104 + tid];
        sX[tid] = s;
    } else if (tid >= 128 && tid < 192) {
        int d = tid - 128;
        sX[100 + d] = user_emb[(size_t)sI[35] * 64 + d];
    }
    __syncthreads();

    // ---- out[b][t] = b2[item] + W2[item] . sX (one warp per t) ----
    if (wid < 3) {
        int it = sI[32 + wid];
        const float* w2p = W2 + (size_t)it * 164;
        float s = 0.0f;
        for (int j = lane; j < 164; j += 32) s = fmaf(w2p[j], sX[j], s);
        #pragma unroll
        for (int off = 16; off; off >>= 1)
            s += __shfl_down_sync(0xffffffffu, s, off);
        if (lane == 0) out[b * 3 + wid] = b2[it] + s;
    }
}

extern "C" void kernel_launch(void* const* d_in, const int* in_sizes, int n_in,
                              void* d_out, int out_size) {
    (void)in_sizes; (void)n_in; (void)out_size;
    cudaFuncSetAttribute(cosrec_kernel,
                         cudaFuncAttributeMaxDynamicSharedMemorySize, SMEM_TOTAL);
    cosrec_kernel<<<512, THREADS, SMEM_TOTAL>>>(
        (const int*)d_in[0],    // seq_var
        (const int*)d_in[1],    // user_var
        (const int*)d_in[2],    // item_var
        (const float*)d_in[3],  // item_emb
        (const float*)d_in[4],  // user_emb
        (const float*)d_in[5],  // W2
        (const float*)d_in[6],  // b2
        (const float*)d_in[7],  // W1
        (const float*)d_in[8],  // b1
        (const float*)d_in[9],  // Wf2
        (const float*)d_in[10], // bf2
        (float*)d_out);
}

// round 8
// speedup vs baseline: 1.1738x; 1.1738x over previous
#include <cuda_runtime.h>
#include <cuda_fp16.h>
#include <stdint.h>

// CosRec fused kernel — fp16 mma.sync (HMMA), round 8.
// = round-5 structure (shared-staged W1 phase 2, single-acc 8-m-tile mainloop,
//   regs ~121 -> 2 CTAs/SM) + round-6/7 conflict-free transposed half2 tables.

#define THREADS 256
#define TSTR 60            // table row stride in words (conflict-free: 60%32=28)

// ---- shared memory byte offsets ----
#define OFF_SI    0        // 36 ints
#define OFF_SX    160      // 164 floats (ends 816)
#define OFF_A2    1024     // uint32 A-table [32 c][60] = 7680 B
#define OFF_B2    8704     // uint32 B-table [32 a][60] = 7680 B
#define OFF_X     16384    // region X: W1 staging 25600 B, then bfragW 23296 B
#define OFF_AF    41984    // fp32 A [100 f][32 c] = 12800 B
#define OFF_BF    54784    // fp32 B [100 f][32 a] = 12800 B
#define OFF_ET    67584    // fp32 E^T [64][33] = 8448 B ; later sRedW[8][104]
#define SMEM_TOTAL 76032

__device__ __forceinline__ void mma16816(float* d, uint32_t a0, uint32_t a1,
                                         uint32_t a2, uint32_t a3,
                                         uint32_t b0, uint32_t b1) {
    asm volatile(
        "mma.sync.aligned.m16n8k16.row.col.f32.f16.f16.f32 "
        "{%0,%1,%2,%3}, {%4,%5,%6,%7}, {%8,%9}, {%0,%1,%2,%3};"
        : "+f"(d[0]), "+f"(d[1]), "+f"(d[2]), "+f"(d[3])
        : "r"(a0), "r"(a1), "r"(a2), "r"(a3), "r"(b0), "r"(b1));
}

__device__ __forceinline__ uint32_t hbuild(uint32_t a, uint32_t b) {
    __half2 av = *reinterpret_cast<__half2*>(&a);
    __half2 bv = *reinterpret_cast<__half2*>(&b);
    __half2 r  = __hmax2(__hadd2(av, bv), __float2half2_rn(0.0f));
    return *reinterpret_cast<uint32_t*>(&r);
}

__global__ __launch_bounds__(THREADS, 2)
void cosrec_kernel(
    const int*   __restrict__ seq_var,   // [512*32]
    const int*   __restrict__ user_var,  // [512]
    const int*   __restrict__ item_var,  // [512*3]
    const float* __restrict__ item_emb,  // [100000*64]
    const float* __restrict__ user_emb,  // [100000*64]
    const float* __restrict__ W2,        // [100000*164]
    const float* __restrict__ b2,        // [100000]
    const float* __restrict__ W1,        // [100*128]
    const float* __restrict__ b1,        // [100]
    const float* __restrict__ Wf2,       // [100*100]
    const float* __restrict__ bf2,       // [100]
    float*       __restrict__ out)       // [512*3]
{
    extern __shared__ char smem[];
    int*      sI  = (int*)(smem + OFF_SI);
    float*    sX  = (float*)(smem + OFF_SX);
    uint32_t* uA2 = (uint32_t*)(smem + OFF_A2);
    uint32_t* uB2 = (uint32_t*)(smem + OFF_B2);
    float*    sAf = (float*)(smem + OFF_AF);
    float*    sBf = (float*)(smem + OFF_BF);
    float*    sEt = (float*)(smem + OFF_ET);

    const int b    = blockIdx.x;
    const int tid  = threadIdx.x;
    const int wid  = tid >> 5;
    const int lane = tid & 31;

    // ---- phase 0: indices ----
    if (tid < 32)       sI[tid] = seq_var[b * 32 + tid];
    else if (tid < 35)  sI[tid] = item_var[b * 3 + (tid - 32)];
    else if (tid == 35) sI[35]  = user_var[b];
    __syncthreads();

    // ---- phase 1: gather E^T ----
    for (int idx = tid; idx < 2048; idx += THREADS) {
        int l = idx >> 6, d = idx & 63;
        sEt[d * 33 + l] = item_emb[(size_t)sI[l] * 64 + d];
    }

    // ---- phase 2: A = E@Wa^T + b1, B = E@Wb^T (W1 staged in region X) ----
    float* sW1c = (float*)(smem + OFF_X);  // [100][64]
    for (int c = 0; c < 2; ++c) {
        __syncthreads();
        for (int idx = tid; idx < 6400; idx += THREADS) {
            int f = idx >> 6, jj = idx & 63;
            int half_ = jj >> 5, j = jj & 31;
            sW1c[idx] = W1[f * 128 + half_ * 64 + c * 32 + j];
        }
        __syncthreads();
        for (int idx = tid; idx < 3200; idx += THREADS) {
            int f = idx >> 5, l = idx & 31;
            float accA = 0.0f, accB = 0.0f;
            #pragma unroll
            for (int j = 0; j < 32; ++j) {
                float e = sEt[(c * 32 + j) * 33 + l];
                accA = fmaf(e, sW1c[f * 64 + j],      accA);
                accB = fmaf(e, sW1c[f * 64 + 32 + j], accB);
            }
            if (c == 0) { sAf[idx] = accA;          sBf[idx] = accB; }
            else        { sAf[idx] += accA + b1[f]; sBf[idx] += accB; }
        }
    }
    __syncthreads();

    // ---- phase 3a: pack half2 tables, transposed [c][k2], stride 60 ----
    // k2 < 50: real (k=2*k2, 2*k2+1). k2 == 50: bias col (A=(1,0), B=(0,0)).
    // k2 in (50,56): zero padding.
    for (int idx = tid; idx < 32 * 56; idx += THREADS) {
        int c = idx / 56, kk = idx - c * 56;
        __half2 va, vb;
        if (kk < 50) {
            va = __floats2half2_rn(sAf[(2 * kk) * 32 + c], sAf[(2 * kk + 1) * 32 + c]);
            vb = __floats2half2_rn(sBf[(2 * kk) * 32 + c], sBf[(2 * kk + 1) * 32 + c]);
        } else if (kk == 50) {
            va = __floats2half2_rn(1.0f, 0.0f);
            vb = __float2half2_rn(0.0f);
        } else {
            va = __float2half2_rn(0.0f);
            vb = __float2half2_rn(0.0f);
        }
        uA2[c * TSTR + kk] = *reinterpret_cast<uint32_t*>(&va);
        uB2[c * TSTR + kk] = *reinterpret_cast<uint32_t*>(&vb);
    }
    __syncthreads();   // W1 staging dead; bfragW overlays region X

    // ---- phase 3b: pack Wf2 B-fragments (mma fragment order, col-major B) ----
    // W(n,k): n<100 & k<100 -> Wf2[n][k]; n<100 & k==100 -> bf2[n]; else 0.
    uint2* bfragW = (uint2*)(smem + OFF_X);
    for (int idx = tid; idx < 13 * 7 * 32; idx += THREADS) {
        int nt  = idx / 224;
        int rem = idx - nt * 224;
        int ks  = rem >> 5, ln = rem & 31;
        int n   = nt * 8 + (ln >> 2);
        int k0  = ks * 16 + (ln & 3) * 2;
        float w0, w1, w2v, w3v;
        if (n < 100) {
            const float* wr = Wf2 + n * 100;
            w0  = (k0     < 100) ? wr[k0]     : ((k0     == 100) ? bf2[n] : 0.0f);
            w1  = (k0 + 1 < 100) ? wr[k0 + 1] : ((k0 + 1 == 100) ? bf2[n] : 0.0f);
            w2v = (k0 + 8 < 100) ? wr[k0 + 8] : ((k0 + 8 == 100) ? bf2[n] : 0.0f);
            w3v = (k0 + 9 < 100) ? wr[k0 + 9] : ((k0 + 9 == 100) ? bf2[n] : 0.0f);
        } else {
            w0 = w1 = w2v = w3v = 0.0f;
        }
        __half2 lo = __floats2half2_rn(w0, w1);
        __half2 hi = __floats2half2_rn(w2v, w3v);
        uint2 val;
        val.x = *reinterpret_cast<uint32_t*>(&lo);
        val.y = *reinterpret_cast<uint32_t*>(&hi);
        bfragW[idx] = val;
    }
    __syncthreads();

    // ---- mainloop: 8 m-tiles of 16 pairs per warp; no CTA syncs ----
    const int gid = lane >> 2;   // row group 0..7
    const int tig = lane & 3;    // k group 0..3

    float xacc[26];
    #pragma unroll
    for (int j = 0; j < 26; ++j) xacc[j] = 0.0f;

    for (int mt = 0; mt < 8; ++mt) {
        // pair p0 = wid*128 + mt*16 + gid, p1 = p0 + 8; same a-block, c split.
        const int p0 = wid * 128 + mt * 16 + gid;
        const int aI = p0 >> 5;
        const int cA = p0 & 31;
        const int cB = cA + 8;

        float acc[13][4];
        #pragma unroll
        for (int nt = 0; nt < 13; ++nt)
            #pragma unroll
            for (int e = 0; e < 4; ++e) acc[nt][e] = 0.0f;

        #pragma unroll
        for (int ks = 0; ks < 7; ++ks) {
            const int k2a = ks * 8 + tig;
            const int k2b = k2a + 4;
            uint32_t Ba = uB2[aI * TSTR + k2a];
            uint32_t Bb = uB2[aI * TSTR + k2b];
            uint32_t a0 = hbuild(uA2[cA * TSTR + k2a], Ba);
            uint32_t a1 = hbuild(uA2[cB * TSTR + k2a], Ba);
            uint32_t a2 = hbuild(uA2[cA * TSTR + k2b], Bb);
            uint32_t a3 = hbuild(uA2[cB * TSTR + k2b], Bb);
            #pragma unroll
            for (int nt = 0; nt < 13; ++nt) {
                uint2 bb = bfragW[(nt * 7 + ks) * 32 + lane];
                mma16816(acc[nt], a0, a1, a2, a3, bb.x, bb.y);
            }
        }
        // relu + colsum into registers (rows p0 and p1)
        #pragma unroll
        for (int nt = 0; nt < 13; ++nt) {
            xacc[nt * 2]     += fmaxf(acc[nt][0], 0.0f) + fmaxf(acc[nt][2], 0.0f);
            xacc[nt * 2 + 1] += fmaxf(acc[nt][1], 0.0f) + fmaxf(acc[nt][3], 0.0f);
        }
    }

    // ---- reduction: shfl over row/k groups, then fixed-order over warps ----
    #pragma unroll
    for (int j = 0; j < 26; ++j) {
        float s = xacc[j];
        s += __shfl_down_sync(0xffffffffu, s, 16);
        s += __shfl_down_sync(0xffffffffu, s, 8);
        s += __shfl_down_sync(0xffffffffu, s, 4);
        xacc[j] = s;
    }
    float* sRedW = (float*)(smem + OFF_ET);  // [8][104], overlays dead E^T
    if (lane < 4) {
        #pragma unroll
        for (int nt = 0; nt < 13; ++nt) {
            int n0 = nt * 8 + lane * 2;      // lane == tig here
            sRedW[wid * 104 + n0]     = xacc[nt * 2];
            sRedW[wid * 104 + n0 + 1] = xacc[nt * 2 + 1];
        }
    }
    __syncthreads();
    if (tid < 100) {
        float s = 0.0f;
        #pragma unroll
        for (int w = 0; w < 8; ++w) s += sRedW[w * 104 + tid];
        sX[tid] = s;
    } else if (tid >= 128 && tid < 192) {
        int d = tid - 128;
        sX[100 + d] = user_emb[(size_t)sI[35] * 64 + d];
    }
    __syncthreads();

    // ---- out[b][t] = b2[item] + W2[item] . sX (one warp per t) ----
    if (wid < 3) {
        int it = sI[32 + wid];
        const float* w2p = W2 + (size_t)it * 164;
        float s = 0.0f;
        for (int j = lane; j < 164; j += 32) s = fmaf(w2p[j], sX[j], s);
        #pragma unroll
        for (int off = 16; off; off >>= 1)
            s += __shfl_down_sync(0xffffffffu, s, off);
        if (lane == 0) out[b * 3 + wid] = b2[it] + s;
    }
}

extern "C" void kernel_launch(void* const* d_in, const int* in_sizes, int n_in,
                              void* d_out, int out_size) {
    (void)in_sizes; (void)n_in; (void)out_size;
    cudaFuncSetAttribute(cosrec_kernel,
                         cudaFuncAttributeMaxDynamicSharedMemorySize, SMEM_TOTAL);
    cosrec_kernel<<<512, THREADS, SMEM_TOTAL>>>(
        (const int*)d_in[0],    // seq_var
        (const int*)d_in[1],    // user_var
        (const int*)d_in[2],    // item_var
        (const float*)d_in[3],  // item_emb
        (const float*)d_in[4],  // user_emb
        (const float*)d_in[5],  // W2
        (const float*)d_in[6],  // b2
        (const float*)d_in[7],  // W1
        (const float*)d_in[8],  // b1
        (const float*)d_in[9],  // Wf2
        (const float*)d_in[10], // bf2
        (float*)d_out);
}